// round 1
// baseline (speedup 1.0000x reference)
#include <cuda_runtime.h>
#include <cuda_bf16.h>

// out[n] = prod_f sigmoid(10*(x[n,f]*w[f]+b[f]))^(1/2)
//        = rsqrt( prod_f (1 + exp(-10*(x*w+b))) )
// Fold -10*log2(e) into w', b' so inner loop is fma + ex2 + fma per element.
// Half-warp per row: 16 lanes x float4 = 64 floats = one row; warp does 2 rows/iter.

#ifndef GRID_BLOCKS
#define GRID_BLOCKS 1184   // 148 SMs * 8
#endif

__global__ __launch_bounds__(256, 8)
void one_to_one_prod_kernel(const float* __restrict__ x,
                            const float* __restrict__ w,
                            const float* __restrict__ b,
                            float* __restrict__ out,
                            long long n_rows)
{
    const int lane  = threadIdx.x & 31;
    const int half  = lane >> 4;       // which row of the pair
    const int hlane = lane & 15;       // lane within half-warp

    // Per-lane feature slice: features [hlane*4, hlane*4+4)
    // Pre-scale: exp(-10*t) = exp2(t * (-10*log2(e)))
    const float NEG10_LOG2E = -14.4269504088896340736f; // -10 / ln(2)
    float4 w4 = reinterpret_cast<const float4*>(w)[hlane];
    float4 b4 = reinterpret_cast<const float4*>(b)[hlane];
    w4.x *= NEG10_LOG2E; w4.y *= NEG10_LOG2E; w4.z *= NEG10_LOG2E; w4.w *= NEG10_LOG2E;
    b4.x *= NEG10_LOG2E; b4.y *= NEG10_LOG2E; b4.z *= NEG10_LOG2E; b4.w *= NEG10_LOG2E;

    const long long warp_id = (long long)blockIdx.x * (blockDim.x >> 5) + (threadIdx.x >> 5);
    const long long n_warps = (long long)gridDim.x * (blockDim.x >> 5);
    const long long n_pairs = n_rows >> 1;

    for (long long p = warp_id; p < n_pairs; p += n_warps) {
        const long long row = 2 * p + half;
        const float4 v = reinterpret_cast<const float4*>(x + row * 64)[hlane];

        // arg_i = (-10*log2e) * (v_i*w_i + b_i);  e_i = 2^arg_i
        float e0 = exp2f(fmaf(v.x, w4.x, b4.x));
        float e1 = exp2f(fmaf(v.y, w4.y, b4.y));
        float e2 = exp2f(fmaf(v.z, w4.z, b4.z));
        float e3 = exp2f(fmaf(v.w, w4.w, b4.w));

        // local product of (1+e_i)
        float pr = (1.0f + e0) * (1.0f + e1) * (1.0f + e2) * (1.0f + e3);

        // factor = rsqrt of the 4-element group product
        float f = rsqrtf(pr);

        // multiply-reduce across the 16-lane half-warp
        #pragma unroll
        for (int off = 8; off > 0; off >>= 1)
            f *= __shfl_xor_sync(0xFFFFFFFFu, f, off, 16);

        if (hlane == 0)
            out[row] = f;
    }
}

extern "C" void kernel_launch(void* const* d_in, const int* in_sizes, int n_in,
                              void* d_out, int out_size)
{
    const float* x = (const float*)d_in[0];   // [N, 64]
    const float* w = (const float*)d_in[1];   // [64]
    const float* b = (const float*)d_in[2];   // [64]
    float* out = (float*)d_out;               // [N]

    const long long n_rows = (long long)in_sizes[0] / 64;

    one_to_one_prod_kernel<<<GRID_BLOCKS, 256>>>(x, w, b, out, n_rows);
}

// round 2
// speedup vs baseline: 1.1644x; 1.1644x over previous
#include <cuda_runtime.h>
#include <cuda_bf16.h>

// out[n] = prod_f sigmoid(10*(x[n,f]*w[f]+b[f]))^(1/2)
//        = rsqrt( prod_f (1 + exp2( (x*w+b) * (-10*log2 e) )) )
// Half-warp (16 lanes x float4) covers one 64-float row; a warp covers 2 rows
// per load. Unroll x2: each warp-iter loads 2 independent LDG.128 (rows
// 4q..4q+3 = 1 KB) front-batched for MLP, then runs two interleaved
// MUFU/SHFL chains so EX2/RSQ/SHFL latency overlaps.

#ifndef GRID_BLOCKS
#define GRID_BLOCKS 1184   // 148 SMs * 8 CTAs
#endif

__global__ __launch_bounds__(256, 8)
void one_to_one_prod_kernel(const float* __restrict__ x,
                            const float* __restrict__ w,
                            const float* __restrict__ b,
                            float* __restrict__ out,
                            long long n_rows)
{
    const int lane  = threadIdx.x & 31;
    const int half  = lane >> 4;       // which row of a pair
    const int hlane = lane & 15;       // lane within half-warp

    const float NEG10_LOG2E = -14.4269504088896340736f; // -10 * log2(e)
    float4 w4 = reinterpret_cast<const float4*>(w)[hlane];
    float4 b4 = reinterpret_cast<const float4*>(b)[hlane];
    w4.x *= NEG10_LOG2E; w4.y *= NEG10_LOG2E; w4.z *= NEG10_LOG2E; w4.w *= NEG10_LOG2E;
    b4.x *= NEG10_LOG2E; b4.y *= NEG10_LOG2E; b4.z *= NEG10_LOG2E; b4.w *= NEG10_LOG2E;

    const long long warp_id = (long long)blockIdx.x * (blockDim.x >> 5) + (threadIdx.x >> 5);
    const long long n_warps = (long long)gridDim.x * (blockDim.x >> 5);
    const long long n_quads = n_rows >> 2;      // 4 rows per warp-iter

    for (long long q = warp_id; q < n_quads; q += n_warps) {
        const long long row0 = 4 * q + half;        // rows row0, row0+2
        const float4* p0 = reinterpret_cast<const float4*>(x + row0 * 64);
        const float4* p1 = reinterpret_cast<const float4*>(x + (row0 + 2) * 64);

        // Front-batch both loads (MLP=2 per warp)
        const float4 v0 = __ldcs(p0 + hlane);
        const float4 v1 = __ldcs(p1 + hlane);

        // Chain 0
        float a0 = exp2f(fmaf(v0.x, w4.x, b4.x));
        float a1 = exp2f(fmaf(v0.y, w4.y, b4.y));
        float a2 = exp2f(fmaf(v0.z, w4.z, b4.z));
        float a3 = exp2f(fmaf(v0.w, w4.w, b4.w));
        // Chain 1 (independent — overlaps MUFU latency)
        float c0 = exp2f(fmaf(v1.x, w4.x, b4.x));
        float c1 = exp2f(fmaf(v1.y, w4.y, b4.y));
        float c2 = exp2f(fmaf(v1.z, w4.z, b4.z));
        float c3 = exp2f(fmaf(v1.w, w4.w, b4.w));

        float pr0 = (1.0f + a0) * (1.0f + a1) * (1.0f + a2) * (1.0f + a3);
        float pr1 = (1.0f + c0) * (1.0f + c1) * (1.0f + c2) * (1.0f + c3);

        float f0 = rsqrtf(pr0);
        float f1 = rsqrtf(pr1);

        // Interleaved multiply-reductions across each 16-lane half-warp
        #pragma unroll
        for (int off = 8; off > 0; off >>= 1) {
            f0 *= __shfl_xor_sync(0xFFFFFFFFu, f0, off, 16);
            f1 *= __shfl_xor_sync(0xFFFFFFFFu, f1, off, 16);
        }

        if (hlane == 0) {
            // lanes 0 and 16 write rows row0 and row0+1 / row0+2 and row0+3:
            // 4 adjacent floats -> single 16B sector
            __stcs(out + row0,     f0);
            __stcs(out + row0 + 2, f1);
        }
    }

    // Tail (n_rows not divisible by 4): handle leftover rows pair-wise.
    const long long tail_start = n_quads * 4;
    if (tail_start < n_rows) {
        const long long n_pairs_tail = (n_rows - tail_start) >> 1;
        for (long long t = warp_id; t < n_pairs_tail; t += n_warps) {
            const long long row = tail_start + 2 * t + half;
            const float4 v = __ldcs(reinterpret_cast<const float4*>(x + row * 64) + hlane);
            float e0 = exp2f(fmaf(v.x, w4.x, b4.x));
            float e1 = exp2f(fmaf(v.y, w4.y, b4.y));
            float e2 = exp2f(fmaf(v.z, w4.z, b4.z));
            float e3 = exp2f(fmaf(v.w, w4.w, b4.w));
            float f = rsqrtf((1.0f + e0) * (1.0f + e1) * (1.0f + e2) * (1.0f + e3));
            #pragma unroll
            for (int off = 8; off > 0; off >>= 1)
                f *= __shfl_xor_sync(0xFFFFFFFFu, f, off, 16);
            if (hlane == 0) out[row] = f;
        }
        // odd final row: let warp 0 do it scalar-ish
        if ((n_rows - tail_start) & 1) {
            if (warp_id == 0) {
                const long long row = n_rows - 1;
                const float4 v = __ldcs(reinterpret_cast<const float4*>(x + row * 64) + hlane);
                float e0 = exp2f(fmaf(v.x, w4.x, b4.x));
                float e1 = exp2f(fmaf(v.y, w4.y, b4.y));
                float e2 = exp2f(fmaf(v.z, w4.z, b4.z));
                float e3 = exp2f(fmaf(v.w, w4.w, b4.w));
                float f = rsqrtf((1.0f + e0) * (1.0f + e1) * (1.0f + e2) * (1.0f + e3));
                #pragma unroll
                for (int off = 8; off > 0; off >>= 1)
                    f *= __shfl_xor_sync(0xFFFFFFFFu, f, off, 32);
                if (lane == 0) out[row] = f;
            }
        }
    }
}

extern "C" void kernel_launch(void* const* d_in, const int* in_sizes, int n_in,
                              void* d_out, int out_size)
{
    const float* x = (const float*)d_in[0];   // [N, 64]
    const float* w = (const float*)d_in[1];   // [64]
    const float* b = (const float*)d_in[2];   // [64]
    float* out = (float*)d_out;               // [N]

    const long long n_rows = (long long)in_sizes[0] / 64;

    one_to_one_prod_kernel<<<GRID_BLOCKS, 256>>>(x, w, b, out, n_rows);
}